// round 12
// baseline (speedup 1.0000x reference)
#include <cuda_runtime.h>
#include <cstdint>

// Problem-size upper bounds (fixed by the dataset).
#define NMAX 100000
#define EMAX 1600000
#define NB_MAX ((NMAX + 1023) / 1024)   // 98 scan blocks

// ---------------------------------------------------------------------------
// Static device scratch (allocation-free per harness rules).
// ---------------------------------------------------------------------------
__device__ float g_t1 [NMAX * 128];  // layer1 msgs t1 = x@W_l1^T ; reused as layer2 u (ld 64)
__device__ float g_pre[NMAX * 128];  // layer1 pre = x@W_r1^T ; becomes h in-place
__device__ int   g_src [EMAX];       // decoded edge sources
__device__ int   g_dst [EMAX];       // decoded edge destinations
__device__ int   g_cnt [NMAX];       // in-degree counters
__device__ int   g_rowptr[NMAX + 1]; // CSR row pointers (by dst)
__device__ int   g_fill[NMAX];       // fill cursors for reorder
__device__ int   g_eidx[EMAX];       // CSR: src indices sorted by dst
__device__ int   g_bsum[NB_MAX];     // scan block sums
__device__ int   g_boff[NB_MAX];     // scan block offsets
__device__ int   g_is64;             // 1 if edge_index is int64, 0 if int32

// ---------------------------------------------------------------------------
// tf32 helpers
// ---------------------------------------------------------------------------
__device__ __forceinline__ uint32_t f2tf(float x) {
    uint32_t r;
    asm("cvt.rna.tf32.f32 %0, %1;" : "=r"(r) : "f"(x));
    return r;
}

__device__ __forceinline__ void mma_tf32(float c[4],
                                         uint32_t a0, uint32_t a1, uint32_t a2, uint32_t a3,
                                         uint32_t b0, uint32_t b1) {
    asm volatile(
        "mma.sync.aligned.m16n8k8.row.col.f32.tf32.tf32.f32 "
        "{%0,%1,%2,%3}, {%4,%5,%6,%7}, {%8,%9}, {%0,%1,%2,%3};"
        : "+f"(c[0]), "+f"(c[1]), "+f"(c[2]), "+f"(c[3])
        : "r"(a0), "r"(a1), "r"(a2), "r"(a3), "r"(b0), "r"(b1));
}

// ---------------------------------------------------------------------------
// Detect edge_index dtype (int64 little-endian has zero high words).
// ---------------------------------------------------------------------------
__global__ void detect_kernel(const int* __restrict__ ei32) {
    if (threadIdx.x == 0 && blockIdx.x == 0) {
        int nz = 0;
        #pragma unroll
        for (int i = 1; i < 128; i += 2) nz |= ei32[i];
        g_is64 = (nz == 0) ? 1 : 0;
    }
}

__global__ void zero_cnt(int N) {
    int i = blockIdx.x * blockDim.x + threadIdx.x;
    if (i < N) g_cnt[i] = 0;
}

// ---------------------------------------------------------------------------
// Decode indices + count in-degrees.
// ---------------------------------------------------------------------------
__global__ void decode_kernel(const void* __restrict__ ei, int E) {
    int e = blockIdx.x * blockDim.x + threadIdx.x;
    if (e >= E) return;
    int src, dst;
    if (g_is64) {
        const long long* p = (const long long*)ei;
        src = (int)p[e];
        dst = (int)p[E + e];
    } else {
        const int* p = (const int*)ei;
        src = p[e];
        dst = p[E + e];
    }
    g_src[e] = src;
    g_dst[e] = dst;
    atomicAdd(&g_cnt[dst], 1);
}

// ---------------------------------------------------------------------------
// 3-kernel exclusive prefix scan of g_cnt -> g_rowptr
// ---------------------------------------------------------------------------
__global__ void scan_block(int N) {
    __shared__ int sh[1024];
    int t = threadIdx.x;
    int i = blockIdx.x * 1024 + t;
    int v = (i < N) ? g_cnt[i] : 0;
    sh[t] = v;
    __syncthreads();
    #pragma unroll
    for (int off = 1; off < 1024; off <<= 1) {
        int x = (t >= off) ? sh[t - off] : 0;
        __syncthreads();
        sh[t] += x;
        __syncthreads();
    }
    if (i < N) g_rowptr[i] = sh[t] - v;
    if (t == 1023) g_bsum[blockIdx.x] = sh[1023];
}

__global__ void scan_partials(int nb) {
    __shared__ int sh[1024];
    int t = threadIdx.x;
    int v = (t < nb) ? g_bsum[t] : 0;
    sh[t] = v;
    __syncthreads();
    #pragma unroll
    for (int off = 1; off < 1024; off <<= 1) {
        int x = (t >= off) ? sh[t - off] : 0;
        __syncthreads();
        sh[t] += x;
        __syncthreads();
    }
    if (t < nb) g_boff[t] = sh[t] - v;
}

__global__ void scan_add(int N, int E) {
    int i = blockIdx.x * blockDim.x + threadIdx.x;
    if (i < N) {
        int val = g_rowptr[i] + g_boff[i >> 10];
        g_rowptr[i] = val;
        g_fill[i]   = val;
    }
    if (i == 0) g_rowptr[N] = E;
}

__global__ void reorder_kernel(int E) {
    int e = blockIdx.x * blockDim.x + threadIdx.x;
    if (e >= E) return;
    int dst = g_dst[e];
    int pos = atomicAdd(&g_fill[dst], 1);
    g_eidx[pos] = g_src[e];
}

// ---------------------------------------------------------------------------
// Tensor-core dual-output GEMM: C = A[N,128] @ Wcat^T, K = 128.
// Weights split into tf32 hi+lo in-kernel; only A truncation remains.
// Smem holds fragments in FRAGMENT-MAJOR order: one LDS.128 per mma fragment.
//   A frag (m16k8):  sA[(mtile*2+k8)*32 + lane][reg], reg = a0..a3
//   B frag (n8k8):   sB[(ntile*2+k8)*32 + lane][reg], reg = bh0,bh1,bl0,bl1
// MMA schedule per k8: all 16 hi-MMAs, then all 16 lo-MMAs (dep distance 16).
// LAYER==1: Wcat = [W_l1;W_r1] (grid.y=2), out0=g_t1 (ld128), out1=g_pre (ld128)
// LAYER==2: Wcat = [W_l2;W_r2] (grid.y=1), out0=g_t1 (ld64),  out1=d_out (ld64)
// ---------------------------------------------------------------------------
template <int LAYER>
__global__ __launch_bounds__(256) void gemm_tc(
    const float* __restrict__ Aext,
    const float* __restrict__ W0,
    const float* __restrict__ W1,
    float* __restrict__ outExt,
    int N)
{
    constexpr int n0 = (LAYER == 1) ? 128 : 64;
    constexpr int LD = (LAYER == 1) ? 128 : 64;
    const float* A    = (LAYER == 1) ? Aext : g_pre;
    float*       out0 = g_t1;
    float*       out1 = (LAYER == 1) ? g_pre : outExt;

    // fragment-major smem: A 8 mtiles x 2 k8 x 32 lanes x 4 regs = 2048 u32
    //                      B 16 ntiles x 2 k8 x 32 lanes x 4 regs = 4096 u32
    __shared__ uint32_t sA[2048];
    __shared__ uint32_t sB[4096];

    const int tid  = threadIdx.x;
    const int lane = tid & 31;
    const int wid  = tid >> 5;
    const int wm   = wid >> 2;              // 0..1 warp row (64 rows)
    const int wn   = wid & 3;               // 0..3 warp col (32 cols)
    const int gq   = lane >> 2;             // 0..7
    const int q    = lane & 3;              // 0..3

    const int rowBase = blockIdx.x * 128;
    const int jBase   = blockIdx.y * 128;

    // staging: thread t -> row sr = t>>1, 8 cols at cb = (t&1)*8 (one k8 slice)
    const int sr = tid >> 1;
    const int cb = (tid & 1) * 8;
    const int k8s = cb >> 3;                // which k8 slice this thread stages

    const int  gr     = rowBase + sr;
    const bool avalid = gr < N;
    const float* arow = A + (size_t)gr * 128;
    const float* wrow;
    {
        int jr = jBase + sr;
        wrow = (jr < n0) ? (W0 + (size_t)jr * 128) : (W1 + (size_t)(jr - n0) * 128);
    }

    // fragment-major staging bases (per thread, constant across kt)
    const int mtile = sr >> 4, agrp = sr & 7, ahi = (sr >> 3) & 1;
    uint32_t* paBase = sA + (mtile * 2 + k8s) * 128;         // [lane][reg], 32*4
    const int ntile = sr >> 3, ngrp = sr & 7;
    uint32_t* pbBase = sB + (ntile * 2 + k8s) * 128;

    float c[4][4][4];
    #pragma unroll
    for (int tm = 0; tm < 4; tm++)
        #pragma unroll
        for (int tn = 0; tn < 4; tn++)
            #pragma unroll
            for (int i = 0; i < 4; i++) c[tm][tn][i] = 0.0f;

    // preload tile kt=0
    float4 a0v = avalid ? *(const float4*)(arow + cb)     : make_float4(0.f,0.f,0.f,0.f);
    float4 a1v = avalid ? *(const float4*)(arow + cb + 4) : make_float4(0.f,0.f,0.f,0.f);
    float4 w0v = *(const float4*)(wrow + cb);
    float4 w1v = *(const float4*)(wrow + cb + 4);

    #pragma unroll 1
    for (int kt = 0; kt < 8; kt++) {
        __syncthreads();   // previous compute done before overwriting smem
        {
            float av[8] = {a0v.x, a0v.y, a0v.z, a0v.w, a1v.x, a1v.y, a1v.z, a1v.w};
            float wf[8] = {w0v.x, w0v.y, w0v.z, w0v.w, w1v.x, w1v.y, w1v.z, w1v.w};
            #pragma unroll
            for (int j = 0; j < 8; j++) {
                int jq = j & 3, jh = j >> 2;           // q, khi within k8
                // A: lane = agrp*4+jq, reg = ahi + 2*jh
                paBase[(agrp * 4 + jq) * 4 + ahi + 2 * jh] = f2tf(av[j]);
                // B: lane = ngrp*4+jq, regs: hi->jh, lo->2+jh
                uint32_t hv = f2tf(wf[j]);
                pbBase[(ngrp * 4 + jq) * 4 + jh]     = hv;
                pbBase[(ngrp * 4 + jq) * 4 + 2 + jh] = f2tf(wf[j] - __uint_as_float(hv));
            }
        }
        __syncthreads();

        // issue next tile's global loads (hidden behind compute)
        if (kt < 7) {
            const int k0 = (kt + 1) * 16;
            a0v = avalid ? *(const float4*)(arow + k0 + cb)
                         : make_float4(0.f,0.f,0.f,0.f);
            a1v = avalid ? *(const float4*)(arow + k0 + cb + 4)
                         : make_float4(0.f,0.f,0.f,0.f);
            w0v = *(const float4*)(wrow + k0 + cb);
            w1v = *(const float4*)(wrow + k0 + cb + 4);
        }

        #pragma unroll
        for (int k8 = 0; k8 < 2; k8++) {
            uint4 af[4], bf[4];
            #pragma unroll
            for (int tm = 0; tm < 4; tm++)
                af[tm] = *(const uint4*)&sA[(((wm * 4 + tm) * 2 + k8) * 32 + lane) * 4];
            #pragma unroll
            for (int tn = 0; tn < 4; tn++)
                bf[tn] = *(const uint4*)&sB[(((wn * 4 + tn) * 2 + k8) * 32 + lane) * 4];

            // hi pass: 16 independent MMAs
            #pragma unroll
            for (int tn = 0; tn < 4; tn++)
                #pragma unroll
                for (int tm = 0; tm < 4; tm++)
                    mma_tf32(c[tm][tn], af[tm].x, af[tm].y, af[tm].z, af[tm].w,
                             bf[tn].x, bf[tn].y);
            // lo pass
            #pragma unroll
            for (int tn = 0; tn < 4; tn++)
                #pragma unroll
                for (int tm = 0; tm < 4; tm++)
                    mma_tf32(c[tm][tn], af[tm].x, af[tm].y, af[tm].z, af[tm].w,
                             bf[tn].z, bf[tn].w);
        }
    }

    // epilogue: thread owns (row,row+8) x (col,col+1) per (tm,tn)
    #pragma unroll
    for (int tn = 0; tn < 4; tn++) {
        int col = jBase + wn * 32 + tn * 8 + q * 2;
        float* obase; int jl;
        if (col < n0) { obase = out0; jl = col;      }
        else          { obase = out1; jl = col - n0; }
        #pragma unroll
        for (int tm = 0; tm < 4; tm++) {
            int row0 = rowBase + wm * 64 + tm * 16 + gq;
            int row1 = row0 + 8;
            if (row0 < N) {
                float2 v = make_float2(c[tm][tn][0], c[tm][tn][1]);
                *(float2*)(obase + (size_t)row0 * LD + jl) = v;
            }
            if (row1 < N) {
                float2 v = make_float2(c[tm][tn][2], c[tm][tn][3]);
                *(float2*)(obase + (size_t)row1 * LD + jl) = v;
            }
        }
    }
}

// ---------------------------------------------------------------------------
// CSR gather + fused finalize. One warp per node.
// LAYER==1 (D=128): h = relu(pre + mean + b1) in-place into g_pre.
// LAYER==2 (D=64):  out += mean + b2.
// ---------------------------------------------------------------------------
template <int LAYER>
__global__ __launch_bounds__(256) void gather_finalize(
    const float* __restrict__ bias,
    float* __restrict__ outExt,
    int N)
{
    int gw   = (blockIdx.x * blockDim.x + threadIdx.x) >> 5;
    int lane = threadIdx.x & 31;
    if (gw >= N) return;

    int start = g_rowptr[gw];
    int end   = g_rowptr[gw + 1];
    float inv = 1.0f / (float)max(end - start, 1);

    if (LAYER == 1) {
        const float* msg = g_t1;
        float4 acc = make_float4(0.f, 0.f, 0.f, 0.f);
        int i = start;
        for (; i + 1 < end; i += 2) {
            int s0 = g_eidx[i];
            int s1 = g_eidx[i + 1];
            float4 v0 = *(const float4*)(msg + (size_t)s0 * 128 + lane * 4);
            float4 v1 = *(const float4*)(msg + (size_t)s1 * 128 + lane * 4);
            acc.x += v0.x; acc.y += v0.y; acc.z += v0.z; acc.w += v0.w;
            acc.x += v1.x; acc.y += v1.y; acc.z += v1.z; acc.w += v1.w;
        }
        if (i < end) {
            int s0 = g_eidx[i];
            float4 v0 = *(const float4*)(msg + (size_t)s0 * 128 + lane * 4);
            acc.x += v0.x; acc.y += v0.y; acc.z += v0.z; acc.w += v0.w;
        }
        size_t off = (size_t)gw * 128 + lane * 4;
        float4 pre = *(const float4*)&g_pre[off];
        float4 b   = *(const float4*)&bias[lane * 4];
        float4 h;
        h.x = fmaxf(pre.x + acc.x * inv + b.x, 0.0f);
        h.y = fmaxf(pre.y + acc.y * inv + b.y, 0.0f);
        h.z = fmaxf(pre.z + acc.z * inv + b.z, 0.0f);
        h.w = fmaxf(pre.w + acc.w * inv + b.w, 0.0f);
        *(float4*)&g_pre[off] = h;
    } else {
        const float* msg = g_t1;   // layer2 messages (ld 64)
        float2 acc = make_float2(0.f, 0.f);
        int i = start;
        for (; i + 1 < end; i += 2) {
            int s0 = g_eidx[i];
            int s1 = g_eidx[i + 1];
            float2 v0 = *(const float2*)(msg + (size_t)s0 * 64 + lane * 2);
            float2 v1 = *(const float2*)(msg + (size_t)s1 * 64 + lane * 2);
            acc.x += v0.x; acc.y += v0.y;
            acc.x += v1.x; acc.y += v1.y;
        }
        if (i < end) {
            int s0 = g_eidx[i];
            float2 v0 = *(const float2*)(msg + (size_t)s0 * 64 + lane * 2);
            acc.x += v0.x; acc.y += v0.y;
        }
        size_t off = (size_t)gw * 64 + lane * 2;
        float2 r = *(const float2*)&outExt[off];
        float2 b = *(const float2*)&bias[lane * 2];
        r.x += acc.x * inv + b.x;
        r.y += acc.y * inv + b.y;
        *(float2*)&outExt[off] = r;
    }
}

// ---------------------------------------------------------------------------
// Launch — kernel launches ONLY (graph-capture-safe).
// ---------------------------------------------------------------------------
extern "C" void kernel_launch(void* const* d_in, const int* in_sizes, int n_in,
                              void* d_out, int out_size)
{
    const float* x   = (const float*)d_in[0];
    const void*  ei  = d_in[1];
    const float* Wl1 = (const float*)d_in[2];
    const float* b1  = (const float*)d_in[3];
    const float* Wr1 = (const float*)d_in[4];
    const float* Wl2 = (const float*)d_in[5];
    const float* b2  = (const float*)d_in[6];
    const float* Wr2 = (const float*)d_in[7];
    float*       out = (float*)d_out;

    const int N  = in_sizes[0] / 128;
    const int E  = in_sizes[1] / 2;
    const int nb = (N + 1023) / 1024;

    // 0) CSR build: zero -> detect -> decode+count -> scan -> reorder  (R9 verbatim)
    zero_cnt<<<(N + 255) / 256, 256>>>(N);
    detect_kernel<<<1, 32>>>((const int*)ei);
    decode_kernel<<<(E + 255) / 256, 256>>>(ei, E);
    scan_block<<<nb, 1024>>>(N);
    scan_partials<<<1, 1024>>>(nb);
    scan_add<<<(N + 255) / 256, 256>>>(N, E);
    reorder_kernel<<<(E + 255) / 256, 256>>>(E);

    // 1) layer-1 transforms (tensor cores): g_t1 = x@W_l1^T ; g_pre = x@W_r1^T
    {
        dim3 grid((N + 127) / 128, 2);
        gemm_tc<1><<<grid, 256>>>(x, Wl1, Wr1, nullptr, N);
    }

    // 2) gather + fused finalize1: g_pre <- relu(pre + mean(t1[nbrs]) + b1)
    gather_finalize<1><<<(N * 32 + 255) / 256, 256>>>(b1, nullptr, N);

    // 3) layer-2 transforms: g_t1 = h@W_l2^T (ld 64) ; out = h@W_r2^T
    {
        dim3 grid((N + 127) / 128, 1);
        gemm_tc<2><<<grid, 256>>>(nullptr, Wl2, Wr2, out, N);
    }

    // 4) gather + fused finalize2: out += mean(u[nbrs]) + b2
    gather_finalize<2><<<(N * 32 + 255) / 256, 256>>>(b2, out, N);
}

// round 13
// speedup vs baseline: 1.7725x; 1.7725x over previous
#include <cuda_runtime.h>
#include <cstdint>

// Problem-size upper bounds (fixed by the dataset).
#define NMAX 100000
#define EMAX 1600000
#define NB_MAX ((NMAX + 1023) / 1024)   // 98 scan blocks

// ---------------------------------------------------------------------------
// Static device scratch (allocation-free per harness rules).
// ---------------------------------------------------------------------------
__device__ float g_t1 [NMAX * 128];  // layer1 msgs t1 = x@W_l1^T ; reused as layer2 u (ld 64)
__device__ float g_pre[NMAX * 128];  // layer1 pre = x@W_r1^T ; becomes h in-place
__device__ int   g_src [EMAX];       // decoded edge sources
__device__ int   g_dst [EMAX];       // decoded edge destinations
__device__ int   g_cnt [NMAX];       // in-degree counters
__device__ int   g_rowptr[NMAX + 1]; // CSR row pointers (by dst)
__device__ int   g_fill[NMAX];       // fill cursors for reorder
__device__ int   g_eidx[EMAX];       // CSR: src indices sorted by dst
__device__ int   g_bsum[NB_MAX];     // scan block sums
__device__ int   g_boff[NB_MAX];     // scan block offsets
__device__ int   g_is64;             // 1 if edge_index is int64, 0 if int32

// ---------------------------------------------------------------------------
// tf32 helpers
// ---------------------------------------------------------------------------
__device__ __forceinline__ uint32_t f2tf(float x) {
    uint32_t r;
    asm("cvt.rna.tf32.f32 %0, %1;" : "=r"(r) : "f"(x));
    return r;
}

__device__ __forceinline__ void mma_tf32(float c[4], const uint32_t a[4],
                                         uint32_t b0, uint32_t b1) {
    asm volatile(
        "mma.sync.aligned.m16n8k8.row.col.f32.tf32.tf32.f32 "
        "{%0,%1,%2,%3}, {%4,%5,%6,%7}, {%8,%9}, {%0,%1,%2,%3};"
        : "+f"(c[0]), "+f"(c[1]), "+f"(c[2]), "+f"(c[3])
        : "r"(a[0]), "r"(a[1]), "r"(a[2]), "r"(a[3]), "r"(b0), "r"(b1));
}

// ---------------------------------------------------------------------------
// Detect edge_index dtype (int64 little-endian has zero high words).
// ---------------------------------------------------------------------------
__global__ void detect_kernel(const int* __restrict__ ei32) {
    if (threadIdx.x == 0 && blockIdx.x == 0) {
        int nz = 0;
        #pragma unroll
        for (int i = 1; i < 128; i += 2) nz |= ei32[i];
        g_is64 = (nz == 0) ? 1 : 0;
    }
}

__global__ void zero_cnt(int N) {
    int i = blockIdx.x * blockDim.x + threadIdx.x;
    if (i < N) g_cnt[i] = 0;
}

// ---------------------------------------------------------------------------
// Decode indices + count in-degrees.
// ---------------------------------------------------------------------------
__global__ void decode_kernel(const void* __restrict__ ei, int E) {
    int e = blockIdx.x * blockDim.x + threadIdx.x;
    if (e >= E) return;
    int src, dst;
    if (g_is64) {
        const long long* p = (const long long*)ei;
        src = (int)p[e];
        dst = (int)p[E + e];
    } else {
        const int* p = (const int*)ei;
        src = p[e];
        dst = p[E + e];
    }
    g_src[e] = src;
    g_dst[e] = dst;
    atomicAdd(&g_cnt[dst], 1);
}

// ---------------------------------------------------------------------------
// 3-kernel exclusive prefix scan of g_cnt -> g_rowptr
// ---------------------------------------------------------------------------
__global__ void scan_block(int N) {
    __shared__ int sh[1024];
    int t = threadIdx.x;
    int i = blockIdx.x * 1024 + t;
    int v = (i < N) ? g_cnt[i] : 0;
    sh[t] = v;
    __syncthreads();
    #pragma unroll
    for (int off = 1; off < 1024; off <<= 1) {
        int x = (t >= off) ? sh[t - off] : 0;
        __syncthreads();
        sh[t] += x;
        __syncthreads();
    }
    if (i < N) g_rowptr[i] = sh[t] - v;
    if (t == 1023) g_bsum[blockIdx.x] = sh[1023];
}

__global__ void scan_partials(int nb) {
    __shared__ int sh[1024];
    int t = threadIdx.x;
    int v = (t < nb) ? g_bsum[t] : 0;
    sh[t] = v;
    __syncthreads();
    #pragma unroll
    for (int off = 1; off < 1024; off <<= 1) {
        int x = (t >= off) ? sh[t - off] : 0;
        __syncthreads();
        sh[t] += x;
        __syncthreads();
    }
    if (t < nb) g_boff[t] = sh[t] - v;
}

__global__ void scan_add(int N, int E) {
    int i = blockIdx.x * blockDim.x + threadIdx.x;
    if (i < N) {
        int val = g_rowptr[i] + g_boff[i >> 10];
        g_rowptr[i] = val;
        g_fill[i]   = val;
    }
    if (i == 0) g_rowptr[N] = E;
}

__global__ void reorder_kernel(int E) {
    int e = blockIdx.x * blockDim.x + threadIdx.x;
    if (e >= E) return;
    int dst = g_dst[e];
    int pos = atomicAdd(&g_fill[dst], 1);
    g_eidx[pos] = g_src[e];
}

// ---------------------------------------------------------------------------
// Tensor-core dual-output GEMM: C = A[N,128] @ Wcat^T, K = 128.
// Single-pass tf32 (A and W both rna-truncated). Legacy mma.sync issue rate
// is the binding constraint on sm_100a, so halving MMA count ~halves time.
// LAYER==1: Wcat = [W_l1;W_r1] (grid.y=2), out0=g_t1 (ld128), out1=g_pre (ld128)
// LAYER==2: Wcat = [W_l2;W_r2] (grid.y=1), out0=g_t1 (ld64),  out1=d_out (ld64)
// BM=BN=128, BK=16, 8 warps; warp tile 64x32 = 4x4 m16n8k8 tiles.
// ---------------------------------------------------------------------------
template <int LAYER>
__global__ __launch_bounds__(256) void gemm_tc(
    const float* __restrict__ Aext,
    const float* __restrict__ W0,
    const float* __restrict__ W1,
    float* __restrict__ outExt,
    int N)
{
    constexpr int n0 = (LAYER == 1) ? 128 : 64;
    constexpr int LD = (LAYER == 1) ? 128 : 64;
    const float* A    = (LAYER == 1) ? Aext : g_pre;
    float*       out0 = g_t1;
    float*       out1 = (LAYER == 1) ? g_pre : outExt;

    constexpr int SL = 20;
    __shared__ uint32_t sA[128 * SL];
    __shared__ uint32_t sB[128 * SL];

    const int tid  = threadIdx.x;
    const int lane = tid & 31;
    const int wid  = tid >> 5;
    const int wm   = wid >> 2;
    const int wn   = wid & 3;
    const int gq   = lane >> 2;
    const int q    = lane & 3;

    const int rowBase = blockIdx.x * 128;
    const int jBase   = blockIdx.y * 128;

    const int sr = tid >> 1;
    const int cb = (tid & 1) * 8;

    const int  gr     = rowBase + sr;
    const bool avalid = gr < N;
    const float* arow = A + (size_t)gr * 128;
    const float* wrow;
    {
        int jr = jBase + sr;
        wrow = (jr < n0) ? (W0 + (size_t)jr * 128) : (W1 + (size_t)(jr - n0) * 128);
    }

    float c[4][4][4];
    #pragma unroll
    for (int tm = 0; tm < 4; tm++)
        #pragma unroll
        for (int tn = 0; tn < 4; tn++)
            #pragma unroll
            for (int i = 0; i < 4; i++) c[tm][tn][i] = 0.0f;

    // preload tile kt=0
    float4 a0v = avalid ? *(const float4*)(arow + cb)     : make_float4(0.f,0.f,0.f,0.f);
    float4 a1v = avalid ? *(const float4*)(arow + cb + 4) : make_float4(0.f,0.f,0.f,0.f);
    float4 w0v = *(const float4*)(wrow + cb);
    float4 w1v = *(const float4*)(wrow + cb + 4);

    #pragma unroll 1
    for (int kt = 0; kt < 8; kt++) {
        __syncthreads();   // previous compute done before overwriting smem
        {
            uint32_t* pa = sA + sr * SL + cb;
            pa[0] = f2tf(a0v.x); pa[1] = f2tf(a0v.y);
            pa[2] = f2tf(a0v.z); pa[3] = f2tf(a0v.w);
            pa[4] = f2tf(a1v.x); pa[5] = f2tf(a1v.y);
            pa[6] = f2tf(a1v.z); pa[7] = f2tf(a1v.w);

            uint32_t* pb = sB + sr * SL + cb;
            pb[0] = f2tf(w0v.x); pb[1] = f2tf(w0v.y);
            pb[2] = f2tf(w0v.z); pb[3] = f2tf(w0v.w);
            pb[4] = f2tf(w1v.x); pb[5] = f2tf(w1v.y);
            pb[6] = f2tf(w1v.z); pb[7] = f2tf(w1v.w);
        }
        __syncthreads();

        // issue next tile's global loads (hidden behind compute)
        if (kt < 7) {
            const int k0 = (kt + 1) * 16;
            a0v = avalid ? *(const float4*)(arow + k0 + cb)
                         : make_float4(0.f,0.f,0.f,0.f);
            a1v = avalid ? *(const float4*)(arow + k0 + cb + 4)
                         : make_float4(0.f,0.f,0.f,0.f);
            w0v = *(const float4*)(wrow + k0 + cb);
            w1v = *(const float4*)(wrow + k0 + cb + 4);
        }

        #pragma unroll
        for (int k8 = 0; k8 < 16; k8 += 8) {
            uint32_t af[4][4];
            #pragma unroll
            for (int tm = 0; tm < 4; tm++) {
                int r = (wm * 64 + tm * 16 + gq) * SL + k8 + q;
                af[tm][0] = sA[r];
                af[tm][1] = sA[r + 8 * SL];
                af[tm][2] = sA[r + 4];
                af[tm][3] = sA[r + 8 * SL + 4];
            }
            #pragma unroll
            for (int tn = 0; tn < 4; tn++) {
                int b = (wn * 32 + tn * 8 + gq) * SL + k8 + q;
                uint32_t b0 = sB[b], b1 = sB[b + 4];
                #pragma unroll
                for (int tm = 0; tm < 4; tm++)
                    mma_tf32(c[tm][tn], af[tm], b0, b1);
            }
        }
    }

    #pragma unroll
    for (int tn = 0; tn < 4; tn++) {
        int col = jBase + wn * 32 + tn * 8 + q * 2;
        float* obase; int jl;
        if (col < n0) { obase = out0; jl = col;      }
        else          { obase = out1; jl = col - n0; }
        #pragma unroll
        for (int tm = 0; tm < 4; tm++) {
            int row0 = rowBase + wm * 64 + tm * 16 + gq;
            int row1 = row0 + 8;
            if (row0 < N) {
                float2 v = make_float2(c[tm][tn][0], c[tm][tn][1]);
                *(float2*)(obase + (size_t)row0 * LD + jl) = v;
            }
            if (row1 < N) {
                float2 v = make_float2(c[tm][tn][2], c[tm][tn][3]);
                *(float2*)(obase + (size_t)row1 * LD + jl) = v;
            }
        }
    }
}

// ---------------------------------------------------------------------------
// CSR gather + fused finalize. One warp per node.
// LAYER==1 (D=128): h = relu(pre + mean + b1) in-place into g_pre.
// LAYER==2 (D=64):  out += mean + b2.
// ---------------------------------------------------------------------------
template <int LAYER>
__global__ __launch_bounds__(256) void gather_finalize(
    const float* __restrict__ bias,
    float* __restrict__ outExt,
    int N)
{
    int gw   = (blockIdx.x * blockDim.x + threadIdx.x) >> 5;
    int lane = threadIdx.x & 31;
    if (gw >= N) return;

    int start = g_rowptr[gw];
    int end   = g_rowptr[gw + 1];
    float inv = 1.0f / (float)max(end - start, 1);

    if (LAYER == 1) {
        const float* msg = g_t1;
        float4 acc = make_float4(0.f, 0.f, 0.f, 0.f);
        int i = start;
        for (; i + 1 < end; i += 2) {
            int s0 = g_eidx[i];
            int s1 = g_eidx[i + 1];
            float4 v0 = *(const float4*)(msg + (size_t)s0 * 128 + lane * 4);
            float4 v1 = *(const float4*)(msg + (size_t)s1 * 128 + lane * 4);
            acc.x += v0.x; acc.y += v0.y; acc.z += v0.z; acc.w += v0.w;
            acc.x += v1.x; acc.y += v1.y; acc.z += v1.z; acc.w += v1.w;
        }
        if (i < end) {
            int s0 = g_eidx[i];
            float4 v0 = *(const float4*)(msg + (size_t)s0 * 128 + lane * 4);
            acc.x += v0.x; acc.y += v0.y; acc.z += v0.z; acc.w += v0.w;
        }
        size_t off = (size_t)gw * 128 + lane * 4;
        float4 pre = *(const float4*)&g_pre[off];
        float4 b   = *(const float4*)&bias[lane * 4];
        float4 h;
        h.x = fmaxf(pre.x + acc.x * inv + b.x, 0.0f);
        h.y = fmaxf(pre.y + acc.y * inv + b.y, 0.0f);
        h.z = fmaxf(pre.z + acc.z * inv + b.z, 0.0f);
        h.w = fmaxf(pre.w + acc.w * inv + b.w, 0.0f);
        *(float4*)&g_pre[off] = h;
    } else {
        const float* msg = g_t1;   // layer2 messages (ld 64)
        float2 acc = make_float2(0.f, 0.f);
        int i = start;
        for (; i + 1 < end; i += 2) {
            int s0 = g_eidx[i];
            int s1 = g_eidx[i + 1];
            float2 v0 = *(const float2*)(msg + (size_t)s0 * 64 + lane * 2);
            float2 v1 = *(const float2*)(msg + (size_t)s1 * 64 + lane * 2);
            acc.x += v0.x; acc.y += v0.y;
            acc.x += v1.x; acc.y += v1.y;
        }
        if (i < end) {
            int s0 = g_eidx[i];
            float2 v0 = *(const float2*)(msg + (size_t)s0 * 64 + lane * 2);
            acc.x += v0.x; acc.y += v0.y;
        }
        size_t off = (size_t)gw * 64 + lane * 2;
        float2 r = *(const float2*)&outExt[off];
        float2 b = *(const float2*)&bias[lane * 2];
        r.x += acc.x * inv + b.x;
        r.y += acc.y * inv + b.y;
        *(float2*)&outExt[off] = r;
    }
}

// ---------------------------------------------------------------------------
// Launch — kernel launches ONLY (graph-capture-safe).
// ---------------------------------------------------------------------------
extern "C" void kernel_launch(void* const* d_in, const int* in_sizes, int n_in,
                              void* d_out, int out_size)
{
    const float* x   = (const float*)d_in[0];
    const void*  ei  = d_in[1];
    const float* Wl1 = (const float*)d_in[2];
    const float* b1  = (const float*)d_in[3];
    const float* Wr1 = (const float*)d_in[4];
    const float* Wl2 = (const float*)d_in[5];
    const float* b2  = (const float*)d_in[6];
    const float* Wr2 = (const float*)d_in[7];
    float*       out = (float*)d_out;

    const int N  = in_sizes[0] / 128;
    const int E  = in_sizes[1] / 2;
    const int nb = (N + 1023) / 1024;

    // 0) CSR build: zero -> detect -> decode+count -> scan -> reorder
    zero_cnt<<<(N + 255) / 256, 256>>>(N);
    detect_kernel<<<1, 32>>>((const int*)ei);
    decode_kernel<<<(E + 255) / 256, 256>>>(ei, E);
    scan_block<<<nb, 1024>>>(N);
    scan_partials<<<1, 1024>>>(nb);
    scan_add<<<(N + 255) / 256, 256>>>(N, E);
    reorder_kernel<<<(E + 255) / 256, 256>>>(E);

    // 1) layer-1 transforms (tensor cores): g_t1 = x@W_l1^T ; g_pre = x@W_r1^T
    {
        dim3 grid((N + 127) / 128, 2);
        gemm_tc<1><<<grid, 256>>>(x, Wl1, Wr1, nullptr, N);
    }

    // 2) gather + fused finalize1: g_pre <- relu(pre + mean(t1[nbrs]) + b1)
    gather_finalize<1><<<(N * 32 + 255) / 256, 256>>>(b1, nullptr, N);

    // 3) layer-2 transforms: g_t1 = h@W_l2^T (ld 64) ; out = h@W_r2^T
    {
        dim3 grid((N + 127) / 128, 1);
        gemm_tc<2><<<grid, 256>>>(nullptr, Wl2, Wr2, out, N);
    }

    // 4) gather + fused finalize2: out += mean(u[nbrs]) + b2
    gather_finalize<2><<<(N * 32 + 255) / 256, 256>>>(b2, out, N);
}

// round 16
// speedup vs baseline: 1.8824x; 1.0620x over previous
#include <cuda_runtime.h>
#include <cuda_fp16.h>
#include <cstdint>

// Problem-size upper bounds (fixed by the dataset).
#define NMAX 100000
#define EMAX 1600000
#define NB_MAX ((NMAX + 1023) / 1024)   // 98 scan blocks

// ---------------------------------------------------------------------------
// Static device scratch (allocation-free per harness rules).
// ---------------------------------------------------------------------------
__device__ __half g_t1h[NMAX * 128]; // messages in fp16: layer1 ld128, layer2 ld64
__device__ float  g_pre[NMAX * 128]; // layer1 pre = x@W_r1^T ; becomes h in-place
__device__ int    g_src [EMAX];
__device__ int    g_dst [EMAX];
__device__ int    g_cnt [NMAX];
__device__ int    g_rowptr[NMAX + 1];
__device__ int    g_fill[NMAX];
__device__ int    g_eidx[EMAX];
__device__ int    g_bsum[NB_MAX];
__device__ int    g_boff[NB_MAX];
__device__ int    g_is64;

// ---------------------------------------------------------------------------
// tf32 helpers
// ---------------------------------------------------------------------------
__device__ __forceinline__ uint32_t f2tf(float x) {
    uint32_t r;
    asm("cvt.rna.tf32.f32 %0, %1;" : "=r"(r) : "f"(x));
    return r;
}

__device__ __forceinline__ void mma_tf32(float c[4], const uint32_t a[4],
                                         uint32_t b0, uint32_t b1) {
    asm volatile(
        "mma.sync.aligned.m16n8k8.row.col.f32.tf32.tf32.f32 "
        "{%0,%1,%2,%3}, {%4,%5,%6,%7}, {%8,%9}, {%0,%1,%2,%3};"
        : "+f"(c[0]), "+f"(c[1]), "+f"(c[2]), "+f"(c[3])
        : "r"(a[0]), "r"(a[1]), "r"(a[2]), "r"(a[3]), "r"(b0), "r"(b1));
}

// ---------------------------------------------------------------------------
// CSR build (unchanged from R13 passer)
// ---------------------------------------------------------------------------
__global__ void detect_kernel(const int* __restrict__ ei32) {
    if (threadIdx.x == 0 && blockIdx.x == 0) {
        int nz = 0;
        #pragma unroll
        for (int i = 1; i < 128; i += 2) nz |= ei32[i];
        g_is64 = (nz == 0) ? 1 : 0;
    }
}

__global__ void zero_cnt(int N) {
    int i = blockIdx.x * blockDim.x + threadIdx.x;
    if (i < N) g_cnt[i] = 0;
}

__global__ void decode_kernel(const void* __restrict__ ei, int E) {
    int e = blockIdx.x * blockDim.x + threadIdx.x;
    if (e >= E) return;
    int src, dst;
    if (g_is64) {
        const long long* p = (const long long*)ei;
        src = (int)p[e];
        dst = (int)p[E + e];
    } else {
        const int* p = (const int*)ei;
        src = p[e];
        dst = p[E + e];
    }
    g_src[e] = src;
    g_dst[e] = dst;
    atomicAdd(&g_cnt[dst], 1);
}

__global__ void scan_block(int N) {
    __shared__ int sh[1024];
    int t = threadIdx.x;
    int i = blockIdx.x * 1024 + t;
    int v = (i < N) ? g_cnt[i] : 0;
    sh[t] = v;
    __syncthreads();
    #pragma unroll
    for (int off = 1; off < 1024; off <<= 1) {
        int x = (t >= off) ? sh[t - off] : 0;
        __syncthreads();
        sh[t] += x;
        __syncthreads();
    }
    if (i < N) g_rowptr[i] = sh[t] - v;
    if (t == 1023) g_bsum[blockIdx.x] = sh[1023];
}

__global__ void scan_partials(int nb) {
    __shared__ int sh[1024];
    int t = threadIdx.x;
    int v = (t < nb) ? g_bsum[t] : 0;
    sh[t] = v;
    __syncthreads();
    #pragma unroll
    for (int off = 1; off < 1024; off <<= 1) {
        int x = (t >= off) ? sh[t - off] : 0;
        __syncthreads();
        sh[t] += x;
        __syncthreads();
    }
    if (t < nb) g_boff[t] = sh[t] - v;
}

__global__ void scan_add(int N, int E) {
    int i = blockIdx.x * blockDim.x + threadIdx.x;
    if (i < N) {
        int val = g_rowptr[i] + g_boff[i >> 10];
        g_rowptr[i] = val;
        g_fill[i]   = val;
    }
    if (i == 0) g_rowptr[N] = E;
}

__global__ void reorder_kernel(int E) {
    int e = blockIdx.x * blockDim.x + threadIdx.x;
    if (e >= E) return;
    int dst = g_dst[e];
    int pos = atomicAdd(&g_fill[dst], 1);
    g_eidx[pos] = g_src[e];
}

// ---------------------------------------------------------------------------
// Tensor-core dual-output GEMM: C = A[N,128] @ Wcat^T, K = 128.
// Single-pass tf32 (R13 structure). Message output (cols < n0) stored fp16
// into g_t1h; residual output (cols >= n0) stored fp32.
// LAYER==1: Wcat = [W_l1;W_r1] (grid.y=2), out0=g_t1h (ld128), out1=g_pre (ld128)
// LAYER==2: Wcat = [W_l2;W_r2] (grid.y=1), out0=g_t1h (ld64),  out1=d_out (ld64)
// BM=BN=128, BK=16, 8 warps; warp tile 64x32 = 4x4 m16n8k8 tiles.
// ---------------------------------------------------------------------------
template <int LAYER>
__global__ __launch_bounds__(256) void gemm_tc(
    const float* __restrict__ Aext,
    const float* __restrict__ W0,
    const float* __restrict__ W1,
    float* __restrict__ outExt,
    int N)
{
    constexpr int n0 = (LAYER == 1) ? 128 : 64;
    constexpr int LD = (LAYER == 1) ? 128 : 64;
    const float* A    = (LAYER == 1) ? Aext : g_pre;
    __half*      out0 = g_t1h;
    float*       out1 = (LAYER == 1) ? g_pre : outExt;

    constexpr int SL = 20;
    __shared__ uint32_t sA[128 * SL];
    __shared__ uint32_t sB[128 * SL];

    const int tid  = threadIdx.x;
    const int lane = tid & 31;
    const int wid  = tid >> 5;
    const int wm   = wid >> 2;
    const int wn   = wid & 3;
    const int gq   = lane >> 2;
    const int q    = lane & 3;

    const int rowBase = blockIdx.x * 128;
    const int jBase   = blockIdx.y * 128;

    const int sr = tid >> 1;
    const int cb = (tid & 1) * 8;

    const int  gr     = rowBase + sr;
    const bool avalid = gr < N;
    const float* arow = A + (size_t)gr * 128;
    const float* wrow;
    {
        int jr = jBase + sr;
        wrow = (jr < n0) ? (W0 + (size_t)jr * 128) : (W1 + (size_t)(jr - n0) * 128);
    }

    float c[4][4][4];
    #pragma unroll
    for (int tm = 0; tm < 4; tm++)
        #pragma unroll
        for (int tn = 0; tn < 4; tn++)
            #pragma unroll
            for (int i = 0; i < 4; i++) c[tm][tn][i] = 0.0f;

    // preload tile kt=0
    float4 a0v = avalid ? *(const float4*)(arow + cb)     : make_float4(0.f,0.f,0.f,0.f);
    float4 a1v = avalid ? *(const float4*)(arow + cb + 4) : make_float4(0.f,0.f,0.f,0.f);
    float4 w0v = *(const float4*)(wrow + cb);
    float4 w1v = *(const float4*)(wrow + cb + 4);

    #pragma unroll 1
    for (int kt = 0; kt < 8; kt++) {
        __syncthreads();   // previous compute done before overwriting smem
        {
            uint32_t* pa = sA + sr * SL + cb;
            pa[0] = f2tf(a0v.x); pa[1] = f2tf(a0v.y);
            pa[2] = f2tf(a0v.z); pa[3] = f2tf(a0v.w);
            pa[4] = f2tf(a1v.x); pa[5] = f2tf(a1v.y);
            pa[6] = f2tf(a1v.z); pa[7] = f2tf(a1v.w);

            uint32_t* pb = sB + sr * SL + cb;
            pb[0] = f2tf(w0v.x); pb[1] = f2tf(w0v.y);
            pb[2] = f2tf(w0v.z); pb[3] = f2tf(w0v.w);
            pb[4] = f2tf(w1v.x); pb[5] = f2tf(w1v.y);
            pb[6] = f2tf(w1v.z); pb[7] = f2tf(w1v.w);
        }
        __syncthreads();

        // issue next tile's global loads (hidden behind compute)
        if (kt < 7) {
            const int k0 = (kt + 1) * 16;
            a0v = avalid ? *(const float4*)(arow + k0 + cb)
                         : make_float4(0.f,0.f,0.f,0.f);
            a1v = avalid ? *(const float4*)(arow + k0 + cb + 4)
                         : make_float4(0.f,0.f,0.f,0.f);
            w0v = *(const float4*)(wrow + k0 + cb);
            w1v = *(const float4*)(wrow + k0 + cb + 4);
        }

        #pragma unroll
        for (int k8 = 0; k8 < 16; k8 += 8) {
            uint32_t af[4][4];
            #pragma unroll
            for (int tm = 0; tm < 4; tm++) {
                int r = (wm * 64 + tm * 16 + gq) * SL + k8 + q;
                af[tm][0] = sA[r];
                af[tm][1] = sA[r + 8 * SL];
                af[tm][2] = sA[r + 4];
                af[tm][3] = sA[r + 8 * SL + 4];
            }
            #pragma unroll
            for (int tn = 0; tn < 4; tn++) {
                int b = (wn * 32 + tn * 8 + gq) * SL + k8 + q;
                uint32_t b0 = sB[b], b1 = sB[b + 4];
                #pragma unroll
                for (int tm = 0; tm < 4; tm++)
                    mma_tf32(c[tm][tn], af[tm], b0, b1);
            }
        }
    }

    // epilogue: thread owns (row,row+8) x (col,col+1) per (tm,tn)
    #pragma unroll
    for (int tn = 0; tn < 4; tn++) {
        int col = jBase + wn * 32 + tn * 8 + q * 2;
        bool toMsg = (col < n0);
        int  jl    = toMsg ? col : col - n0;
        #pragma unroll
        for (int tm = 0; tm < 4; tm++) {
            int row0 = rowBase + wm * 64 + tm * 16 + gq;
            int row1 = row0 + 8;
            if (row0 < N) {
                if (toMsg) {
                    __half2 v = __floats2half2_rn(c[tm][tn][0], c[tm][tn][1]);
                    *(__half2*)(out0 + (size_t)row0 * LD + jl) = v;
                } else {
                    float2 v = make_float2(c[tm][tn][0], c[tm][tn][1]);
                    *(float2*)(out1 + (size_t)row0 * LD + jl) = v;
                }
            }
            if (row1 < N) {
                if (toMsg) {
                    __half2 v = __floats2half2_rn(c[tm][tn][2], c[tm][tn][3]);
                    *(__half2*)(out0 + (size_t)row1 * LD + jl) = v;
                } else {
                    float2 v = make_float2(c[tm][tn][2], c[tm][tn][3]);
                    *(float2*)(out1 + (size_t)row1 * LD + jl) = v;
                }
            }
        }
    }
}

// ---------------------------------------------------------------------------
// CSR gather + fused finalize. One warp per node. Messages are fp16.
// LAYER==1 (D=128): lane covers cols lane*4..lane*4+3 (uint2 = 4 halves/edge);
//   h = relu(pre + mean + b1) in-place into g_pre (fp32).
// LAYER==2 (D=64):  lane covers cols lane*2..lane*2+1 (half2 = 4B/edge);
//   out += mean + b2.
// ---------------------------------------------------------------------------
template <int LAYER>
__global__ __launch_bounds__(256) void gather_finalize(
    const float* __restrict__ bias,
    float* __restrict__ outExt,
    int N)
{
    int gw   = (blockIdx.x * blockDim.x + threadIdx.x) >> 5;
    int lane = threadIdx.x & 31;
    if (gw >= N) return;

    int start = g_rowptr[gw];
    int end   = g_rowptr[gw + 1];
    float inv = 1.0f / (float)max(end - start, 1);

    if (LAYER == 1) {
        const __half* msg = g_t1h;
        float4 acc = make_float4(0.f, 0.f, 0.f, 0.f);
        int i = start;
        for (; i + 1 < end; i += 2) {
            int s0 = g_eidx[i];
            int s1 = g_eidx[i + 1];
            uint2 r0 = *(const uint2*)(msg + (size_t)s0 * 128 + lane * 4);
            uint2 r1 = *(const uint2*)(msg + (size_t)s1 * 128 + lane * 4);
            float2 a0 = __half22float2(*(const __half2*)&r0.x);
            float2 b0 = __half22float2(*(const __half2*)&r0.y);
            float2 a1 = __half22float2(*(const __half2*)&r1.x);
            float2 b1 = __half22float2(*(const __half2*)&r1.y);
            acc.x += a0.x + a1.x; acc.y += a0.y + a1.y;
            acc.z += b0.x + b1.x; acc.w += b0.y + b1.y;
        }
        if (i < end) {
            int s0 = g_eidx[i];
            uint2 r0 = *(const uint2*)(msg + (size_t)s0 * 128 + lane * 4);
            float2 a0 = __half22float2(*(const __half2*)&r0.x);
            float2 b0 = __half22float2(*(const __half2*)&r0.y);
            acc.x += a0.x; acc.y += a0.y; acc.z += b0.x; acc.w += b0.y;
        }
        size_t off = (size_t)gw * 128 + lane * 4;
        float4 pre = *(const float4*)&g_pre[off];
        float4 b   = *(const float4*)&bias[lane * 4];
        float4 h;
        h.x = fmaxf(pre.x + acc.x * inv + b.x, 0.0f);
        h.y = fmaxf(pre.y + acc.y * inv + b.y, 0.0f);
        h.z = fmaxf(pre.z + acc.z * inv + b.z, 0.0f);
        h.w = fmaxf(pre.w + acc.w * inv + b.w, 0.0f);
        *(float4*)&g_pre[off] = h;
    } else {
        const __half* msg = g_t1h;   // layer2 messages (ld 64)
        float2 acc = make_float2(0.f, 0.f);
        int i = start;
        for (; i + 1 < end; i += 2) {
            int s0 = g_eidx[i];
            int s1 = g_eidx[i + 1];
            float2 v0 = __half22float2(*(const __half2*)(msg + (size_t)s0 * 64 + lane * 2));
            float2 v1 = __half22float2(*(const __half2*)(msg + (size_t)s1 * 64 + lane * 2));
            acc.x += v0.x + v1.x;
            acc.y += v0.y + v1.y;
        }
        if (i < end) {
            int s0 = g_eidx[i];
            float2 v0 = __half22float2(*(const __half2*)(msg + (size_t)s0 * 64 + lane * 2));
            acc.x += v0.x; acc.y += v0.y;
        }
        size_t off = (size_t)gw * 64 + lane * 2;
        float2 r = *(const float2*)&outExt[off];
        float2 b = *(const float2*)&bias[lane * 2];
        r.x += acc.x * inv + b.x;
        r.y += acc.y * inv + b.y;
        *(float2*)&outExt[off] = r;
    }
}

// ---------------------------------------------------------------------------
// Launch — kernel launches ONLY (graph-capture-safe).
// ---------------------------------------------------------------------------
extern "C" void kernel_launch(void* const* d_in, const int* in_sizes, int n_in,
                              void* d_out, int out_size)
{
    const float* x   = (const float*)d_in[0];
    const void*  ei  = d_in[1];
    const float* Wl1 = (const float*)d_in[2];
    const float* b1  = (const float*)d_in[3];
    const float* Wr1 = (const float*)d_in[4];
    const float* Wl2 = (const float*)d_in[5];
    const float* b2  = (const float*)d_in[6];
    const float* Wr2 = (const float*)d_in[7];
    float*       out = (float*)d_out;

    const int N  = in_sizes[0] / 128;
    const int E  = in_sizes[1] / 2;
    const int nb = (N + 1023) / 1024;

    // 0) CSR build: zero -> detect -> decode+count -> scan -> reorder
    zero_cnt<<<(N + 255) / 256, 256>>>(N);
    detect_kernel<<<1, 32>>>((const int*)ei);
    decode_kernel<<<(E + 255) / 256, 256>>>(ei, E);
    scan_block<<<nb, 1024>>>(N);
    scan_partials<<<1, 1024>>>(nb);
    scan_add<<<(N + 255) / 256, 256>>>(N, E);
    reorder_kernel<<<(E + 255) / 256, 256>>>(E);

    // 1) layer-1 transforms (tensor cores): g_t1h = fp16(x@W_l1^T) ; g_pre = x@W_r1^T
    {
        dim3 grid((N + 127) / 128, 2);
        gemm_tc<1><<<grid, 256>>>(x, Wl1, Wr1, nullptr, N);
    }

    // 2) gather + fused finalize1: g_pre <- relu(pre + mean(t1[nbrs]) + b1)
    gather_finalize<1><<<(N * 32 + 255) / 256, 256>>>(b1, nullptr, N);

    // 3) layer-2 transforms: g_t1h = fp16(h@W_l2^T) (ld 64) ; out = h@W_r2^T
    {
        dim3 grid((N + 127) / 128, 1);
        gemm_tc<2><<<grid, 256>>>(nullptr, Wl2, Wr2, out, N);
    }

    // 4) gather + fused finalize2: out += mean(u[nbrs]) + b2
    gather_finalize<2><<<(N * 32 + 255) / 256, 256>>>(b2, out, N);
}